// round 1
// baseline (speedup 1.0000x reference)
#include <cuda_runtime.h>
#include <cuda_bf16.h>

// Embedding gather: out[s, :] = weights[x[s], :]
// x: [8192] int32, weights: [49408, 768] fp32, out: [8192, 768] fp32
// Pure memory-bound: ~50 MB traffic -> ~8 us floor at ~6.3 TB/s.

#define SEQ 8192
#define DIM 768
#define VEC (DIM / 4)   // 192 float4 per row

__global__ void __launch_bounds__(VEC) embed_gather_kernel(
    const int* __restrict__ x,
    const float4* __restrict__ weights,   // [VOCAB, VEC]
    float4* __restrict__ out)             // [SEQ, VEC]
{
    const int s = blockIdx.x;
    const int t = threadIdx.x;
    const int row = x[s];                 // uniform per block, L1-cached
    out[(size_t)s * VEC + t] = weights[(size_t)row * VEC + t];
}

extern "C" void kernel_launch(void* const* d_in, const int* in_sizes, int n_in,
                              void* d_out, int out_size) {
    const int*    x = (const int*)d_in[0];
    const float4* w = (const float4*)d_in[1];
    float4*       o = (float4*)d_out;
    embed_gather_kernel<<<SEQ, VEC>>>(x, w, o);
}

// round 2
// speedup vs baseline: 1.2007x; 1.2007x over previous
#include <cuda_runtime.h>
#include <cuda_bf16.h>

// Embedding gather: out[s, :] = weights[x[s], :]
// x: [8192] int32, weights: [49408, 768] fp32, out: [8192, 768] fp32
// Latency-bound -> batch U rows per CTA for MLP=8 per thread.

#define SEQ 8192
#define DIM 768
#define VEC (DIM / 4)   // 192 float4 per row
#define U   8           // rows per CTA

__global__ void __launch_bounds__(VEC) embed_gather_kernel(
    const int* __restrict__ x,
    const float4* __restrict__ weights,   // [VOCAB, VEC]
    float4* __restrict__ out)             // [SEQ, VEC]
{
    const int t  = threadIdx.x;
    const int s0 = blockIdx.x * U;

    // 8 independent index loads (same addresses across the warp -> broadcast)
    int rows[U];
#pragma unroll
    for (int u = 0; u < U; u++)
        rows[u] = __ldg(&x[s0 + u]);

    // 8 independent 16B gathers in flight per thread
    float4 v[U];
#pragma unroll
    for (int u = 0; u < U; u++)
        v[u] = weights[(size_t)rows[u] * VEC + t];

#pragma unroll
    for (int u = 0; u < U; u++)
        out[(size_t)(s0 + u) * VEC + t] = v[u];
}

extern "C" void kernel_launch(void* const* d_in, const int* in_sizes, int n_in,
                              void* d_out, int out_size) {
    const int*    x = (const int*)d_in[0];
    const float4* w = (const float4*)d_in[1];
    float4*       o = (float4*)d_out;
    embed_gather_kernel<<<SEQ / U, VEC>>>(x, w, o);
}